// round 7
// baseline (speedup 1.0000x reference)
#include <cuda_runtime.h>
#include <cstddef>

// Problem constants
#define KB   1024          // batch
#define KL   50            // seq len
#define KE   64            // emb dim
#define KFV  4
#define KFH  16
#define KT   1024
#define KFEAT 1056         // FV*E + FH*L

typedef unsigned int u32;

// ---- scratch (static device globals) ----
__device__ float g_emb[KB * KL * KE];     // gathered item embeddings (fp32)
__device__ float g_feat[KB * KFEAT];      // [out_v | out_h]
__device__ float g_x[KB * 128];           // [z | user_emb]

__device__ __forceinline__ u32 cvt_tf32(float x) {
    u32 r; asm("cvt.rna.tf32.f32 %0, %1;" : "=r"(r) : "f"(x)); return r;
}

// ============================================================
// K1: gather item embeddings + vertical conv (out_v)
// ============================================================
__global__ void k1_gather_outv(const int* __restrict__ seqs,
                               const float* __restrict__ itab,
                               const float* __restrict__ Wv,
                               const float* __restrict__ bv) {
    __shared__ float es[KL * KE];
    __shared__ float wv[KFV * KL];
    int b = blockIdx.x, tid = threadIdx.x;

    for (int idx = tid; idx < KL * KE; idx += 256) {
        int l = idx >> 6, e = idx & 63;
        int item = __ldg(&seqs[b * KL + l]);
        float v = __ldg(&itab[(size_t)item * KE + e]);
        es[idx] = v;
        g_emb[(size_t)b * KL * KE + idx] = v;
    }
    if (tid < KFV * KL) wv[tid] = Wv[tid];
    __syncthreads();

    int f = tid >> 6, e = tid & 63;
    float acc = __ldg(&bv[f]);
#pragma unroll
    for (int l = 0; l < KL; l++)
        acc = fmaf(es[l * KE + e], wv[f * KL + l], acc);
    g_feat[(size_t)b * KFEAT + f * KE + e] = acc;
}

// ============================================================
// K2: horizontal convs via tf32 mma.sync, warps split over K(j)
// grid = (B/2, L); 256 threads = 8 warps.
// warp = (jgrp = w&3, nhalf = w>>2). Warp handles j in
// {chunk+2*jgrp, chunk+2*jgrp+1} for all position tiles ->
// every warp busy for all h >= 8 (the expensive blocks).
// Weights staged in 8-j chunks (2 syncs per chunk).
// Partial accumulators summed across jgrp in smem epilogue,
// then masked max over positions.
// Dynamic smem layout (u32 units):
//   es  [2][65][68]              35360 B
//   ws  [8][16][68]              34816 B
//   part[4][4][2][16][16] float  32768 B   total 102944 B
// ============================================================
#define ES_U32   (2 * 65 * 68)
#define WS_U32   (8 * 16 * 68)
#define PART_F   (4 * 4 * 2 * 16 * 16)
#define K2_SMEM  ((ES_U32 + WS_U32) * 4 + PART_F * 4)

__global__ __launch_bounds__(256) void k2_conv(const float* __restrict__ Wh,
                                               const float* __restrict__ bh) {
    extern __shared__ __align__(16) u32 dyn[];
    u32 (*es)[65][68] = (u32(*)[65][68])dyn;               // [2][65][68]
    u32 (*ws)[16][68] = (u32(*)[16][68])(dyn + ES_U32);    // [8][16][68]
    float* part = (float*)(dyn + ES_U32 + WS_U32);         // [4][4][2][16][16]

    int bp = blockIdx.x, i = blockIdx.y;
    int tid = threadIdx.x, lane = tid & 31, w = tid >> 5;
    int b0 = bp * 2;
    int h = i + 1, P = KL - i;
    int ntiles = (P + 15) >> 4;
    int jgrp = w & 3, nhalf = w >> 2;
    int g = lane >> 2, t = lane & 3;

    // zero es (padding rows) + part
    {
        uint4* z4 = (uint4*)dyn;
        const uint4 zz = make_uint4(0u, 0u, 0u, 0u);
        for (int idx = tid; idx < ES_U32 / 4; idx += 256) z4[idx] = zz;
        uint4* p4 = (uint4*)part;
        for (int idx = tid; idx < PART_F / 4; idx += 256) p4[idx] = zz;
    }
    __syncthreads();

    // fill rows < 50 with tf32-converted embeddings
    {
        const float4* ge4 = (const float4*)g_emb;
        for (int idx = tid; idx < 2 * 50 * 16; idx += 256) {
            int bl = idx / 800;
            int rem = idx - bl * 800;
            int r = rem >> 4, e4 = (rem & 15) << 2;
            float4 v = ge4[((size_t)(b0 + bl) * KL + r) * 16 + (rem & 15)];
            *(uint4*)&es[bl][r][e4] =
                make_uint4(cvt_tf32(v.x), cvt_tf32(v.y), cvt_tf32(v.z), cvt_tf32(v.w));
        }
    }

    float c[4][2][4];
#pragma unroll
    for (int mt = 0; mt < 4; mt++)
#pragma unroll
        for (int bl = 0; bl < 2; bl++)
#pragma unroll
            for (int q = 0; q < 4; q++) c[mt][bl][q] = 0.f;

    int sf = tid >> 4, se4 = (tid & 15) << 2;   // staging role: filter, e-quad
    int nchunk = (h + 7) >> 3;

    for (int ch = 0; ch < nchunk; ch++) {
        int j0 = ch * 8;
        __syncthreads();   // previous chunk's MMAs done (and es fill on ch==0)
        // stage up to 8 j's of weights, coalesced LDG.128
#pragma unroll
        for (int jl = 0; jl < 8; jl++) {
            int j = j0 + jl;
            if (j < h) {
                float4 v = __ldg((const float4*)(Wh + (size_t)(i * KFH + sf) * (KL * KE)
                                                 + j * KE + se4));
                *(uint4*)&ws[jl][sf][se4] =
                    make_uint4(cvt_tf32(v.x), cvt_tf32(v.y), cvt_tf32(v.z), cvt_tf32(v.w));
            }
        }
        __syncthreads();

#pragma unroll
        for (int jl2 = 0; jl2 < 2; jl2++) {
            int jl = jgrp * 2 + jl2;
            int j = j0 + jl;
            if (j >= h) break;
            // B fragments for this j (reused across all mtiles)
            u32 br0[8], br1[8];
            const u32* bpt = &ws[jl][nhalf * 8 + g][t];
#pragma unroll
            for (int s = 0; s < 8; s++) { br0[s] = bpt[s * 8]; br1[s] = bpt[s * 8 + 4]; }
#pragma unroll
            for (int mt = 0; mt < 4; mt++) {
                if (mt >= ntiles) break;
                const u32* a0p = &es[0][mt * 16 + g + j][t];
                const u32* a1p = &es[1][mt * 16 + g + j][t];
#pragma unroll
                for (int s = 0; s < 8; s++) {
                    u32 a0 = a0p[s * 8], a1 = a0p[8 * 68 + s * 8];
                    u32 a2 = a0p[s * 8 + 4], a3 = a0p[8 * 68 + s * 8 + 4];
                    asm volatile(
                        "mma.sync.aligned.m16n8k8.row.col.f32.tf32.tf32.f32 "
                        "{%0,%1,%2,%3}, {%4,%5,%6,%7}, {%8,%9}, {%0,%1,%2,%3};"
                        : "+f"(c[mt][0][0]), "+f"(c[mt][0][1]), "+f"(c[mt][0][2]), "+f"(c[mt][0][3])
                        : "r"(a0), "r"(a1), "r"(a2), "r"(a3), "r"(br0[s]), "r"(br1[s]));
                    u32 d0 = a1p[s * 8], d1 = a1p[8 * 68 + s * 8];
                    u32 d2 = a1p[s * 8 + 4], d3 = a1p[8 * 68 + s * 8 + 4];
                    asm volatile(
                        "mma.sync.aligned.m16n8k8.row.col.f32.tf32.tf32.f32 "
                        "{%0,%1,%2,%3}, {%4,%5,%6,%7}, {%8,%9}, {%0,%1,%2,%3};"
                        : "+f"(c[mt][1][0]), "+f"(c[mt][1][1]), "+f"(c[mt][1][2]), "+f"(c[mt][1][3])
                        : "r"(d0), "r"(d1), "r"(d2), "r"(d3), "r"(br0[s]), "r"(br1[s]));
                }
            }
        }
    }

    // write partial C fragments: part[jgrp][mt][bat][row16][f16]
#pragma unroll
    for (int mt = 0; mt < 4; mt++) {
        if (mt >= ntiles) break;
#pragma unroll
        for (int bl = 0; bl < 2; bl++) {
            float* q = part + ((((jgrp * 4 + mt) * 2 + bl) * 16) + g) * 16 + nhalf * 8 + 2 * t;
            q[0] = c[mt][bl][0];
            q[1] = c[mt][bl][1];
            q[8 * 16] = c[mt][bl][2];
            q[8 * 16 + 1] = c[mt][bl][3];
        }
    }
    __syncthreads();

    // phase A: sum over jgrp, mask invalid, write in-place into part[0] region
    {
        int mt = tid >> 6, bat = (tid >> 5) & 1, pos = (tid >> 1) & 15, f0 = (tid & 1) * 8;
        int eoff = (((mt)*2 + bat) * 16 + pos) * 16 + f0;
        float4 s0 = make_float4(0.f, 0.f, 0.f, 0.f);
        float4 s1 = make_float4(0.f, 0.f, 0.f, 0.f);
#pragma unroll
        for (int jg = 0; jg < 4; jg++) {
            const float4* src = (const float4*)(part + jg * (4 * 2 * 16 * 16) + eoff);
            float4 a = src[0], b = src[1];
            s0.x += a.x; s0.y += a.y; s0.z += a.z; s0.w += a.w;
            s1.x += b.x; s1.y += b.y; s1.z += b.z; s1.w += b.w;
        }
        int gp = mt * 16 + pos;
        bool valid = (mt < ntiles) && (gp < P);
        const float NEG = -3.4e38f;
        float4* dst = (float4*)(part + eoff);
        dst[0] = valid ? s0 : make_float4(NEG, NEG, NEG, NEG);
        dst[1] = valid ? s1 : make_float4(NEG, NEG, NEG, NEG);
    }
    __syncthreads();

    // phase B: max over (mt, pos), relu + bias, store
    if (tid < 32) {
        int bat = tid >> 4, f = tid & 15;
        float m = -3.4e38f;
        for (int mt = 0; mt < ntiles; mt++)
            for (int pos = 0; pos < 16; pos++)
                m = fmaxf(m, part[((mt * 2 + bat) * 16 + pos) * 16 + f]);
        float r = fmaxf(0.f, m + __ldg(&bh[i * KFH + f]));
        g_feat[(size_t)(b0 + bat) * KFEAT + KFV * KE + i * KFH + f] = r;
    }
}

// ============================================================
// K3: z = relu(feat @ W1^T + b1); x = [z, user_emb]
// ============================================================
__global__ void k3_dense(const float* __restrict__ W1,
                         const float* __restrict__ b1,
                         const int* __restrict__ uvar,
                         const float* __restrict__ utab) {
    __shared__ float fs[KFEAT];
    __shared__ float zs[64];
    int b = blockIdx.x, tid = threadIdx.x, lane = tid & 31, w = tid >> 5;

    for (int idx = tid; idx < KFEAT; idx += 256)
        fs[idx] = g_feat[(size_t)b * KFEAT + idx];
    __syncthreads();

#pragma unroll
    for (int q = 0; q < 8; q++) {
        int o = w * 8 + q;
        const float* wr = W1 + (size_t)o * KFEAT;
        float acc = 0.f;
        for (int kk = lane; kk < KFEAT; kk += 32)
            acc = fmaf(fs[kk], __ldg(&wr[kk]), acc);
#pragma unroll
        for (int off = 16; off; off >>= 1)
            acc += __shfl_xor_sync(0xffffffffu, acc, off);
        if (lane == 0) zs[o] = acc;
    }
    __syncthreads();

    if (tid < 64) {
        g_x[(size_t)b * 128 + tid] = fmaxf(0.f, zs[tid] + __ldg(&b1[tid]));
    } else if (tid < 128) {
        int u = __ldg(&uvar[b]);
        g_x[(size_t)b * 128 + tid] = __ldg(&utab[(size_t)u * 64 + (tid - 64)]);
    }
}

// ============================================================
// K4: res[b,t] = dot(W2_table[item], x[b]) + b2_table[item]
// ============================================================
__global__ void k4_score(const int* __restrict__ items,
                         const float* __restrict__ W2,
                         const float* __restrict__ b2t,
                         float* __restrict__ out) {
    int b = blockIdx.x, tid = threadIdx.x, lane = tid & 31, w = tid >> 5;
    float4 x = *(const float4*)&g_x[(size_t)b * 128 + lane * 4];
    const int* ib = items + (size_t)b * KT;
    float* ob = out + (size_t)b * KT;

    int idx_lane = ((lane >> 4) & 1) * 2 + ((lane >> 3) & 1);

    for (int t = w * 4; t < KT; t += 32) {
        int i0 = __ldg(&ib[t]);
        int i1 = __ldg(&ib[t + 1]);
        int i2 = __ldg(&ib[t + 2]);
        int i3 = __ldg(&ib[t + 3]);
        float4 a0 = __ldg((const float4*)(W2 + (size_t)i0 * 128) + lane);
        float4 a1 = __ldg((const float4*)(W2 + (size_t)i1 * 128) + lane);
        float4 a2 = __ldg((const float4*)(W2 + (size_t)i2 * 128) + lane);
        float4 a3 = __ldg((const float4*)(W2 + (size_t)i3 * 128) + lane);
        float v[4];
        v[0] = a0.x * x.x + a0.y * x.y + a0.z * x.z + a0.w * x.w;
        v[1] = a1.x * x.x + a1.y * x.y + a1.z * x.z + a1.w * x.w;
        v[2] = a2.x * x.x + a2.y * x.y + a2.z * x.z + a2.w * x.w;
        v[3] = a3.x * x.x + a3.y * x.y + a3.z * x.z + a3.w * x.w;

#pragma unroll
        for (int m = 16, half = 2; m >= 8; m >>= 1, half >>= 1) {
#pragma unroll
            for (int q = 0; q < 2; q++) {
                if (q >= half) break;
                bool hibit = (lane & m) != 0;
                float send = hibit ? v[q] : v[q + half];
                float recv = __shfl_xor_sync(0xffffffffu, send, m);
                v[q] = (hibit ? v[q + half] : v[q]) + recv;
            }
        }
        v[0] += __shfl_xor_sync(0xffffffffu, v[0], 4);
        v[0] += __shfl_xor_sync(0xffffffffu, v[0], 2);
        v[0] += __shfl_xor_sync(0xffffffffu, v[0], 1);
        if ((lane & 7) == 0) {
            int ii = (idx_lane == 0) ? i0 : (idx_lane == 1) ? i1 : (idx_lane == 2) ? i2 : i3;
            ob[t + idx_lane] = v[0] + __ldg(&b2t[ii]);
        }
    }
}

// ============================================================
extern "C" void kernel_launch(void* const* d_in, const int* in_sizes, int n_in,
                              void* d_out, int out_size) {
    const int*   seqs  = (const int*)d_in[0];
    const int*   items = (const int*)d_in[1];
    const int*   uvar  = (const int*)d_in[2];
    const float* utab  = (const float*)d_in[3];
    const float* itab  = (const float*)d_in[4];
    const float* Wv    = (const float*)d_in[5];
    const float* bv    = (const float*)d_in[6];
    const float* Wh    = (const float*)d_in[7];
    const float* bh    = (const float*)d_in[8];
    const float* W1    = (const float*)d_in[9];
    const float* b1    = (const float*)d_in[10];
    const float* W2    = (const float*)d_in[11];
    const float* b2t   = (const float*)d_in[12];
    float* out = (float*)d_out;

    cudaFuncSetAttribute(k2_conv, cudaFuncAttributeMaxDynamicSharedMemorySize, K2_SMEM);

    k1_gather_outv<<<KB, 256>>>(seqs, itab, Wv, bv);
    k2_conv<<<dim3(KB / 2, KL), 256, K2_SMEM>>>(Wh, bh);
    k3_dense<<<KB, 256>>>(W1, b1, uvar, utab);
    k4_score<<<KB, 256>>>(items, W2, b2t, out);
}